// round 3
// baseline (speedup 1.0000x reference)
#include <cuda_runtime.h>
#include <cuda_fp16.h>
#include <cstdint>

// Problem constants
#define B_    4096
#define LAT_  128
#define SEQ_  512
#define HID_  32
#define OUT_  64

typedef unsigned long long ull;

// ---- fp16 scratch for the hidden-state sequence: 4096*512*32 = 67.1M halves = 134MB
__device__ __half g_hs[(size_t)B_ * SEQ_ * HID_];

__device__ __forceinline__ ull f2fma(ull a, ull b, ull c) {
    ull d;
    asm("fma.rn.f32x2 %0, %1, %2, %3;" : "=l"(d) : "l"(a), "l"(b), "l"(c));
    return d;
}
__device__ __forceinline__ ull f2pack(float lo, float hi) {
    ull r; asm("mov.b64 %0, {%1, %2};" : "=l"(r) : "f"(lo), "f"(hi)); return r;
}
__device__ __forceinline__ float f2sum(ull v) {
    float lo, hi; asm("mov.b64 {%0, %1}, %2;" : "=f"(lo), "=f"(hi) : "l"(v));
    return lo + hi;
}

// sigmoid / tanh via MUFU EX2 + RCP (near-fp32 accuracy, proven 2.7e-7 end-to-end)
__device__ __forceinline__ float sigf(float x) {
    float e = __expf(-x);
    return __fdividef(1.0f, 1.0f + e);
}
__device__ __forceinline__ float tanhf_fast(float x) {
    float e = __expf(-2.0f * x);
    return __fdividef(2.0f, 1.0f + e) - 1.0f;
}

// ============================================================================
// K1: LSTM recurrence. 4 warps/block, 2 batch elements per warp (shared weight
// registers, independent accumulator chains for ILP tail-hiding). Stores h_t
// to g_hs as fp16 each step. No projection work in-loop.
// ============================================================================
#define K1_WARPS 4
#define K1_THREADS (K1_WARPS * 32)
#define K1_ELEMS (K1_WARPS * 2)

__global__ void __launch_bounds__(K1_THREADS, 2)
lstm_recurrence_kernel(const float* __restrict__ z,
                       const float* __restrict__ init_W,
                       const float* __restrict__ init_b,
                       const float* __restrict__ W_hh,
                       const float* __restrict__ b_ih,
                       const float* __restrict__ b_hh)
{
    __shared__ __align__(16) float whh_s[128 * 34];          // 17408 B (pad: conflict-light)
    __shared__ __align__(16) float iwT_s[128 * 32];          // 16384 B (transposed init_W)
    __shared__ __align__(16) float zs[K1_ELEMS * 128];       //  4096 B
    __shared__ __align__(16) float hb[2][K1_ELEMS * 32];     //  2048 B (double-buffered h)

    const int tid = threadIdx.x;
    const int w   = tid >> 5;
    const int j   = tid & 31;
    const int b0  = blockIdx.x * K1_ELEMS + 2 * w;   // this warp's two batch rows
    const int b1  = b0 + 1;

    // ---- stage weights / inputs (coalesced) ----
    for (int i = tid; i < 128 * 32; i += K1_THREADS)
        whh_s[(i >> 5) * 34 + (i & 31)] = W_hh[i];
    for (int i = tid; i < 32 * 128; i += K1_THREADS) {
        int jj = i >> 7, kk = i & 127;
        iwT_s[kk * 32 + jj] = init_W[i];
    }
    for (int i = tid; i < K1_ELEMS * 128; i += K1_THREADS)
        zs[i] = z[(size_t)blockIdx.x * K1_ELEMS * LAT_ + i];
    __syncthreads();

    // ---- gate weight rows for lane j, shared by both elements (128 regs) ----
    ull Wi[16], Wf[16], Wg[16], Wo[16];
#pragma unroll
    for (int m = 0; m < 16; m++) {
        Wi[m] = *reinterpret_cast<const ull*>(&whh_s[(j     ) * 34 + 2 * m]);
        Wf[m] = *reinterpret_cast<const ull*>(&whh_s[(32 + j) * 34 + 2 * m]);
        Wg[m] = *reinterpret_cast<const ull*>(&whh_s[(64 + j) * 34 + 2 * m]);
        Wo[m] = *reinterpret_cast<const ull*>(&whh_s[(96 + j) * 34 + 2 * m]);
    }
    const float bi = b_ih[j]      + b_hh[j];
    const float bf = b_ih[32 + j] + b_hh[32 + j];
    const float bg = b_ih[64 + j] + b_hh[64 + j];
    const float bo = b_ih[96 + j] + b_hh[96 + j];

    // ---- h0 for both elements ----
    float h0v = init_b[j], h1v = h0v;
    {
        const float* z0 = &zs[(2 * w    ) * 128];
        const float* z1 = &zs[(2 * w + 1) * 128];
#pragma unroll 8
        for (int k = 0; k < 128; k++) {
            float wv = iwT_s[k * 32 + j];
            h0v = fmaf(z0[k], wv, h0v);
            h1v = fmaf(z1[k], wv, h1v);
        }
    }
    float c0 = 0.0f, c1 = 0.0f;

    __half* hs0 = g_hs + (size_t)b0 * SEQ_ * HID_ + j;
    __half* hs1 = g_hs + (size_t)b1 * SEQ_ * HID_ + j;

    float* hbw0_base[2] = { &hb[0][(2 * w) * 32],     &hb[1][(2 * w) * 32] };
    float* hbw1_base[2] = { &hb[0][(2 * w + 1) * 32], &hb[1][(2 * w + 1) * 32] };

    // ---- 512-step recurrence ----
    for (int t = 0; t < SEQ_; t++) {
        const int pb = t & 1;
        float* hbw0 = hbw0_base[pb];
        float* hbw1 = hbw1_base[pb];
        hbw0[j] = h0v;
        hbw1[j] = h1v;
        // also store this step's INPUT h (h_t enters gates; y uses h_{t+1}..)
        // note: hs holds h AFTER each step (outputs), stored at tail below.
        __syncwarp();

        ull ai0 = f2pack(bi, 0.f), af0 = f2pack(bf, 0.f);
        ull ag0 = f2pack(bg, 0.f), ao0 = f2pack(bo, 0.f);
        ull ai1 = f2pack(bi, 0.f), af1 = f2pack(bf, 0.f);
        ull ag1 = f2pack(bg, 0.f), ao1 = f2pack(bo, 0.f);
#pragma unroll
        for (int m = 0; m < 16; m++) {
            ull hp0 = *reinterpret_cast<const ull*>(&hbw0[2 * m]);
            ull hp1 = *reinterpret_cast<const ull*>(&hbw1[2 * m]);
            ai0 = f2fma(Wi[m], hp0, ai0);
            ai1 = f2fma(Wi[m], hp1, ai1);
            af0 = f2fma(Wf[m], hp0, af0);
            af1 = f2fma(Wf[m], hp1, af1);
            ag0 = f2fma(Wg[m], hp0, ag0);
            ag1 = f2fma(Wg[m], hp1, ag1);
            ao0 = f2fma(Wo[m], hp0, ao0);
            ao1 = f2fma(Wo[m], hp1, ao1);
        }

        // tails: two independent chains -> ILP
        float I0 = sigf(f2sum(ai0)), I1 = sigf(f2sum(ai1));
        float F0 = sigf(f2sum(af0)), F1 = sigf(f2sum(af1));
        float G0 = tanhf_fast(f2sum(ag0)), G1 = tanhf_fast(f2sum(ag1));
        float O0 = sigf(f2sum(ao0)), O1 = sigf(f2sum(ao1));
        c0 = fmaf(F0, c0, I0 * G0);
        c1 = fmaf(F1, c1, I1 * G1);
        h0v = O0 * tanhf_fast(c0);
        h1v = O1 * tanhf_fast(c1);

        hs0[(size_t)t * HID_] = __float2half(h0v);
        hs1[(size_t)t * HID_] = __float2half(h1v);
        // next iteration writes the OTHER buffer; no second syncwarp needed
    }
}

// ============================================================================
// K2: output projection  y[r, :] = hs[r, :] @ out_W^T + out_b,  r in [0, B*SEQ)
// 8 warps/block; lane j computes outputs 2j, 2j+1 via f32x2 chains.
// ============================================================================
#define K2_WARPS 8
#define K2_THREADS (K2_WARPS * 32)
#define K2_BLOCKS 2048
#define K2_TOTAL_WARPS (K2_BLOCKS * K2_WARPS)

__global__ void __launch_bounds__(K2_THREADS, 2)
proj_kernel(const float* __restrict__ out_W,
            const float* __restrict__ out_b,
            float* __restrict__ y)
{
    __shared__ __align__(16) float outw_s[64 * 34];            // 8704 B
    __shared__ __align__(16) float hrow[2][K2_WARPS * 32];     // 2048 B (double buffer)

    const int tid = threadIdx.x;
    const int w   = tid >> 5;
    const int j   = tid & 31;

    for (int i = tid; i < 64 * 32; i += K2_THREADS)
        outw_s[(i >> 5) * 34 + (i & 31)] = out_W[i];
    __syncthreads();

    // lane j holds out_W rows 2j and 2j+1 as f32x2 pairs (64 regs)
    ull Pa[16], Pb[16];
#pragma unroll
    for (int m = 0; m < 16; m++) {
        Pa[m] = *reinterpret_cast<const ull*>(&outw_s[(2 * j    ) * 34 + 2 * m]);
        Pb[m] = *reinterpret_cast<const ull*>(&outw_s[(2 * j + 1) * 34 + 2 * m]);
    }
    const float ob0 = out_b[2 * j];
    const float ob1 = out_b[2 * j + 1];

    const size_t warp_id  = (size_t)blockIdx.x * K2_WARPS + w;
    const size_t n_rows   = (size_t)B_ * SEQ_;

    for (size_t r = warp_id; r < n_rows; r += K2_TOTAL_WARPS) {
        // load one h row (fp16, 64B coalesced), broadcast via smem
        float hv = __half2float(g_hs[r * HID_ + j]);
        const int pb = (int)((r / K2_TOTAL_WARPS) & 1);
        float* hw = &hrow[pb][w * 32];
        hw[j] = hv;
        __syncwarp();

        ull acc0 = f2pack(ob0, 0.f), acc1 = f2pack(ob1, 0.f);
#pragma unroll
        for (int m = 0; m < 16; m++) {
            ull hp = *reinterpret_cast<const ull*>(&hw[2 * m]);
            acc0 = f2fma(Pa[m], hp, acc0);
            acc1 = f2fma(Pb[m], hp, acc1);
        }
        *reinterpret_cast<ull*>(y + r * OUT_ + 2 * j) =
            f2pack(f2sum(acc0), f2sum(acc1));
    }
}

extern "C" void kernel_launch(void* const* d_in, const int* in_sizes, int n_in,
                              void* d_out, int out_size)
{
    // metadata order: z, init_W, init_b, W_ih, W_hh, b_ih, b_hh, out_W, out_b
    const float* z      = (const float*)d_in[0];
    const float* init_W = (const float*)d_in[1];
    const float* init_b = (const float*)d_in[2];
    // d_in[3] = W_ih: unused (input sequence is all zeros)
    const float* W_hh   = (const float*)d_in[4];
    const float* b_ih   = (const float*)d_in[5];
    const float* b_hh   = (const float*)d_in[6];
    const float* out_W  = (const float*)d_in[7];
    const float* out_b  = (const float*)d_in[8];
    float* y            = (float*)d_out;

    lstm_recurrence_kernel<<<B_ / K1_ELEMS, K1_THREADS>>>(
        z, init_W, init_b, W_hh, b_ih, b_hh);
    proj_kernel<<<K2_BLOCKS, K2_THREADS>>>(out_W, out_b, y);
}

// round 4
// speedup vs baseline: 1.4636x; 1.4636x over previous
#include <cuda_runtime.h>
#include <cstdint>

// Problem constants
#define B_    4096
#define LAT_  128
#define SEQ_  512
#define HID_  32
#define OUT_  64

#define WARPS_PER_BLOCK 8
#define THREADS (WARPS_PER_BLOCK * 32)

typedef unsigned long long ull;

__device__ __forceinline__ ull f2fma(ull a, ull b, ull c) {
    ull d;
    asm("fma.rn.f32x2 %0, %1, %2, %3;" : "=l"(d) : "l"(a), "l"(b), "l"(c));
    return d;
}
__device__ __forceinline__ ull f2pack(float lo, float hi) {
    ull r; asm("mov.b64 %0, {%1, %2};" : "=l"(r) : "f"(lo), "f"(hi)); return r;
}
__device__ __forceinline__ float f2sum(ull v) {
    float lo, hi; asm("mov.b64 {%0, %1}, %2;" : "=f"(lo), "=f"(hi) : "l"(v));
    return lo + hi;
}

// sigmoid / tanh via MUFU EX2 + RCP (proven 2.7e-7 end-to-end in R1)
__device__ __forceinline__ float sigf(float x) {
    float e = __expf(-x);
    return __fdividef(1.0f, 1.0f + e);
}
__device__ __forceinline__ float tanhf_fast(float x) {
    float e = __expf(-2.0f * x);
    return __fdividef(2.0f, 1.0f + e) - 1.0f;
}

__global__ void __launch_bounds__(THREADS, 1)
lstm_decoder_kernel(const float* __restrict__ z,
                    const float* __restrict__ init_W,
                    const float* __restrict__ init_b,
                    const float* __restrict__ W_hh,
                    const float* __restrict__ b_ih,
                    const float* __restrict__ b_hh,
                    const float* __restrict__ out_W,
                    const float* __restrict__ out_b,
                    float* __restrict__ y)
{
    __shared__ __align__(16) float whh_s[128 * 34];   // 17408 B (padded)
    __shared__ __align__(16) float outw_s[64 * 34];   //  8704 B
    __shared__ __align__(16) float iwT_s[128 * 32];   // 16384 B (transposed init_W)
    __shared__ __align__(16) float zs[WARPS_PER_BLOCK * 128];     // 4096 B
    __shared__ __align__(16) float hb[2][WARPS_PER_BLOCK * 32];   // 2048 B (double buffer)

    const int tid  = threadIdx.x;
    const int w    = tid >> 5;      // warp in block
    const int j    = tid & 31;      // lane = hidden unit index
    const int b    = blockIdx.x * WARPS_PER_BLOCK + w;   // batch element

    // ---- stage weights into smem (coalesced global reads) ----
    for (int i = tid; i < 128 * 32; i += THREADS)
        whh_s[(i >> 5) * 34 + (i & 31)] = W_hh[i];
    for (int i = tid; i < 64 * 32; i += THREADS)
        outw_s[(i >> 5) * 34 + (i & 31)] = out_W[i];
    for (int i = tid; i < 32 * 128; i += THREADS) {
        int jj = i >> 7, kk = i & 127;
        iwT_s[kk * 32 + jj] = init_W[i];
    }
    for (int kk = j; kk < 128; kk += 32)
        zs[w * 128 + kk] = z[(size_t)b * LAT_ + kk];
    __syncthreads();

    // ---- per-lane weights into registers as f32x2 pairs (192 regs) ----
    ull Wi[16], Wf[16], Wg[16], Wo[16], Pa[16], Pb[16];
#pragma unroll
    for (int m = 0; m < 16; m++) {
        Wi[m] = *reinterpret_cast<const ull*>(&whh_s[(j      ) * 34 + 2 * m]);
        Wf[m] = *reinterpret_cast<const ull*>(&whh_s[(32 + j ) * 34 + 2 * m]);
        Wg[m] = *reinterpret_cast<const ull*>(&whh_s[(64 + j ) * 34 + 2 * m]);
        Wo[m] = *reinterpret_cast<const ull*>(&whh_s[(96 + j ) * 34 + 2 * m]);
        Pa[m] = *reinterpret_cast<const ull*>(&outw_s[(j     ) * 34 + 2 * m]);
        Pb[m] = *reinterpret_cast<const ull*>(&outw_s[(32 + j) * 34 + 2 * m]);
    }

    // ---- h0 = z @ init_W^T + init_b ----
    float h = init_b[j];
#pragma unroll 8
    for (int k = 0; k < 128; k++)
        h = fmaf(zs[w * 128 + k], iwT_s[k * 32 + j], h);
    float c = 0.0f;

    const float bi  = b_ih[j]       + b_hh[j];
    const float bf  = b_ih[32 + j]  + b_hh[32 + j];
    const float bg  = b_ih[64 + j]  + b_hh[64 + j];
    const float bo  = b_ih[96 + j]  + b_hh[96 + j];
    const float ob0 = out_b[j];
    const float ob1 = out_b[32 + j];

    float* yo = y + (size_t)b * SEQ_ * OUT_;

    // ---- de-convoy stagger: warps 4..7 (the second warp on each SMSP) get a
    // ~256-cycle dependent-FFMA delay so their FFMA bursts interleave with the
    // partner warp's serial tail instead of colliding on the FMA port. ----
    if ((w >> 2) & 1) {
        float d0 = (float)j + 1.0f;
#pragma unroll 1
        for (int i = 0; i < 64; i++)
            asm volatile("fma.rn.f32 %0, %0, %1, %2;"
                         : "+f"(d0) : "f"(1.0f), "f"(0.0f));
    }

    // ---- main recurrence; projection of h_t fused into step t+1's matvec ----
    for (int t = 0; t < SEQ_; t++) {
        float* hbw = &hb[t & 1][w * 32];
        hbw[j] = h;
        __syncwarp();

        ull ai = f2pack(bi, 0.0f), af = f2pack(bf, 0.0f);
        ull ag = f2pack(bg, 0.0f), ao = f2pack(bo, 0.0f);
        ull y0 = f2pack(ob0, 0.0f), y1 = f2pack(ob1, 0.0f);
#pragma unroll
        for (int m = 0; m < 16; m++) {
            ull hp = *reinterpret_cast<const ull*>(&hbw[2 * m]);  // broadcast
            ai = f2fma(Wi[m], hp, ai);
            af = f2fma(Wf[m], hp, af);
            ag = f2fma(Wg[m], hp, ag);
            ao = f2fma(Wo[m], hp, ao);
            y0 = f2fma(Pa[m], hp, y0);
            y1 = f2fma(Pb[m], hp, y1);
        }
        if (t > 0) {   // y[t-1] = proj(h_t)  (h_t entered this step's matvec)
            yo[(t - 1) * OUT_ + j]      = f2sum(y0);
            yo[(t - 1) * OUT_ + 32 + j] = f2sum(y1);
        }

        float gi = f2sum(ai), gf = f2sum(af), gg = f2sum(ag), go = f2sum(ao);
        float I = sigf(gi), F = sigf(gf), G = tanhf_fast(gg), O = sigf(go);
        c = fmaf(F, c, I * G);
        h = O * tanhf_fast(c);
        // next iteration writes the other hb buffer: one syncwarp per step
    }

    // ---- peeled final projection: y[511] = proj(h_512) ----
    {
        float* hbw = &hb[SEQ_ & 1][w * 32];
        hbw[j] = h;
        __syncwarp();
        ull y0 = f2pack(ob0, 0.0f), y1 = f2pack(ob1, 0.0f);
#pragma unroll
        for (int m = 0; m < 16; m++) {
            ull hp = *reinterpret_cast<const ull*>(&hbw[2 * m]);
            y0 = f2fma(Pa[m], hp, y0);
            y1 = f2fma(Pb[m], hp, y1);
        }
        yo[(SEQ_ - 1) * OUT_ + j]      = f2sum(y0);
        yo[(SEQ_ - 1) * OUT_ + 32 + j] = f2sum(y1);
    }
}

extern "C" void kernel_launch(void* const* d_in, const int* in_sizes, int n_in,
                              void* d_out, int out_size)
{
    // metadata order: z, init_W, init_b, W_ih, W_hh, b_ih, b_hh, out_W, out_b
    const float* z      = (const float*)d_in[0];
    const float* init_W = (const float*)d_in[1];
    const float* init_b = (const float*)d_in[2];
    // d_in[3] = W_ih: unused (input sequence is all zeros)
    const float* W_hh   = (const float*)d_in[4];
    const float* b_ih   = (const float*)d_in[5];
    const float* b_hh   = (const float*)d_in[6];
    const float* out_W  = (const float*)d_in[7];
    const float* out_b  = (const float*)d_in[8];
    float* y            = (float*)d_out;

    dim3 grid(B_ / WARPS_PER_BLOCK);   // 512 blocks
    dim3 block(THREADS);               // 8 warps = 8 batch rows
    lstm_decoder_kernel<<<grid, block>>>(z, init_W, init_b, W_hh,
                                         b_ih, b_hh, out_W, out_b, y);
}